// round 14
// baseline (speedup 1.0000x reference)
#include <cuda_runtime.h>
#include <math.h>

// ============================================================================
// Both resize chains begin with nearest 64->16 (pure selection of every 4th
// row/col).  With U = compose(H ops 1..22) (47x16), V = compose(W ops 1..22)
// (30x16):   out[img](47x30) = U * Xg[img] * V^T,  Xg[i][j] = X[4i][4j].
//
// U^T / V^T composed on the HOST and shipped via one H2D memcpy node.
// Main kernel: 128 threads = 4 warps; each warp processes TWO images.
// Image B's gather is issued before image A's math (latency overlap) and
// parked in its OWN smem slab (no buffer reuse hazards).
// ============================================================================

// U^T [i][a] (16x48, a<47 valid) followed by V^T [j][n] (16x32, n<30 valid)
__device__ __align__(16) float g_UV[16 * 48 + 16 * 32];

// ---------------------------------------------------------------------------
// Host-side composition (bit-exact fp32 index math; no FMA contraction).
// ---------------------------------------------------------------------------
static const int h_out[2][23] = {
    {16, 32, 20, 80, 16, 32,  16, 32, 20, 80, 16, 32,
     16, 32, 20, 80, 16, 32,  54, 108, 54, 43, 47},
    {16, 32, 20, 80, 24, 72,  16, 32, 20, 80, 24, 72,
     16, 32, 20, 80, 24, 72,  144, 172, 68, 61, 30}};
static const int h_mode[23] = {0, 0, 0, 0, 0, 0,  1, 1, 1, 1, 1, 1,
                               2, 2, 2, 2, 2, 2,  0, 1, 1, 2, 2};
static const int h_align[23] = {0, 0, 0, 0, 0, 0,  0, 0, 0, 0, 1, 1,
                                0, 0, 0, 0, 1, 1,  0, 0, 1, 0, 1};

static inline float vmul(float a, float b) { volatile float r = a * b; return r; }
static inline float vadd(float a, float b) { volatile float r = a + b; return r; }
static inline float vsub(float a, float b) { volatile float r = a - b; return r; }

static inline float hcc1(float t) {
    float u = vsub(vmul(1.25f, t), 2.25f);
    u = vmul(u, t);
    u = vmul(u, t);
    return vadd(u, 1.0f);
}
static inline float hcc2(float t) {
    float u = vadd(vmul(-0.75f, t), 3.75f);
    u = vsub(vmul(u, t), 6.0f);
    u = vmul(u, t);
    return vadd(u, 3.0f);
}

static void host_build(float* UV) {
    float* Ut = UV;          // 16*48
    float* Vt = UV + 768;    // 16*32
    static float bufA[172 * 16], bufB[172 * 16];
    for (int axis = 0; axis < 2; ++axis) {
        float* cur = bufA;
        float* nxt = bufB;
        for (int i = 0; i < 256; ++i)
            cur[i] = ((i >> 4) == (i & 15)) ? 1.0f : 0.0f;

        int in_n = 16;
        for (int op = 1; op < 23; ++op) {
            const int on = h_out[axis][op];
            const int mode = h_mode[op];
            const int al = h_align[op];
            for (int d = 0; d < on; ++d) {
                int idx[4];
                float w[4];
                if (mode == 0) {
                    float ratio = (float)((double)in_n / (double)on);
                    int i0 = (int)floorf(vmul((float)d, ratio));
                    if (i0 > in_n - 1) i0 = in_n - 1;
                    idx[0] = idx[1] = idx[2] = idx[3] = i0;
                    w[0] = 1.0f; w[1] = w[2] = w[3] = 0.0f;
                } else {
                    float src;
                    if (al) {
                        float ratio = (float)((double)(in_n - 1) / (double)(on - 1));
                        src = vmul((float)d, ratio);
                    } else {
                        float ratio = (float)((double)in_n / (double)on);
                        src = vsub(vmul(vadd((float)d, 0.5f), ratio), 0.5f);
                        if (mode == 1 && src < 0.0f) src = 0.0f;
                    }
                    float x0 = floorf(src);
                    int i0 = (int)x0;
                    float tt = vsub(src, x0);
                    if (mode == 1) {
                        int ia = i0 < 0 ? 0 : (i0 > in_n - 1 ? in_n - 1 : i0);
                        int ib = i0 + 1 > in_n - 1 ? in_n - 1 : i0 + 1;
                        idx[0] = ia; idx[1] = ib; idx[2] = ia; idx[3] = ia;
                        w[0] = 1.0f - tt; w[1] = tt; w[2] = 0.0f; w[3] = 0.0f;
                    } else {
                        int k0 = i0 - 1, k1 = i0, k2 = i0 + 1, k3 = i0 + 2;
                        k0 = k0 < 0 ? 0 : (k0 > in_n - 1 ? in_n - 1 : k0);
                        k1 = k1 < 0 ? 0 : (k1 > in_n - 1 ? in_n - 1 : k1);
                        k2 = k2 < 0 ? 0 : (k2 > in_n - 1 ? in_n - 1 : k2);
                        k3 = k3 < 0 ? 0 : (k3 > in_n - 1 ? in_n - 1 : k3);
                        idx[0] = k0; idx[1] = k1; idx[2] = k2; idx[3] = k3;
                        w[0] = hcc2(vadd(tt, 1.0f));
                        w[1] = hcc1(tt);
                        w[2] = hcc1(vsub(1.0f, tt));
                        w[3] = hcc2(vsub(2.0f, tt));
                    }
                }
                for (int c = 0; c < 16; ++c) {
                    nxt[d * 16 + c] =
                        fmaf(w[3], cur[idx[3] * 16 + c],
                        fmaf(w[2], cur[idx[2] * 16 + c],
                        fmaf(w[1], cur[idx[1] * 16 + c],
                             w[0] * cur[idx[0] * 16 + c])));
                }
            }
            float* tp = cur; cur = nxt; nxt = tp;
            in_n = on;
        }

        if (axis == 0) {
            for (int i = 0; i < 16; ++i)
                for (int a = 0; a < 48; ++a)
                    Ut[i * 48 + a] = (a < 47) ? cur[a * 16 + i] : 0.0f;
        } else {
            for (int j = 0; j < 16; ++j)
                for (int n = 0; n < 32; ++n)
                    Vt[j * 32 + n] = (n < 30) ? cur[n * 16 + j] : 0.0f;
        }
    }
}

// ---------------------------------------------------------------------------
// Device phases (warp-local).
// ---------------------------------------------------------------------------
__device__ __forceinline__ void phase1(const float* __restrict__ sVt,
                                       const float* __restrict__ xgT,
                                       float* __restrict__ tT,
                                       int n4, int i0) {
    float a1[4][4] = {};
    #pragma unroll
    for (int j = 0; j < 16; ++j) {
        const float4 v = *(const float4*)&sVt[j * 32 + n4];
        const float4 xq = *(const float4*)&xgT[j * 20 + i0];
        a1[0][0] = fmaf(xq.x, v.x, a1[0][0]);
        a1[0][1] = fmaf(xq.x, v.y, a1[0][1]);
        a1[0][2] = fmaf(xq.x, v.z, a1[0][2]);
        a1[0][3] = fmaf(xq.x, v.w, a1[0][3]);
        a1[1][0] = fmaf(xq.y, v.x, a1[1][0]);
        a1[1][1] = fmaf(xq.y, v.y, a1[1][1]);
        a1[1][2] = fmaf(xq.y, v.z, a1[1][2]);
        a1[1][3] = fmaf(xq.y, v.w, a1[1][3]);
        a1[2][0] = fmaf(xq.z, v.x, a1[2][0]);
        a1[2][1] = fmaf(xq.z, v.y, a1[2][1]);
        a1[2][2] = fmaf(xq.z, v.z, a1[2][2]);
        a1[2][3] = fmaf(xq.z, v.w, a1[2][3]);
        a1[3][0] = fmaf(xq.w, v.x, a1[3][0]);
        a1[3][1] = fmaf(xq.w, v.y, a1[3][1]);
        a1[3][2] = fmaf(xq.w, v.z, a1[3][2]);
        a1[3][3] = fmaf(xq.w, v.w, a1[3][3]);
    }
    #pragma unroll
    for (int r = 0; r < 4; ++r)
        *(float4*)&tT[(i0 + r) * 36 + n4] =
            make_float4(a1[r][0], a1[r][1], a1[r][2], a1[r][3]);
}

__device__ __forceinline__ void phase2(const float* __restrict__ sUt,
                                       const float* __restrict__ tT,
                                       float* __restrict__ op,
                                       int n4, int a0) {
    float a2[12][4] = {};
    #pragma unroll
    for (int i = 0; i < 16; ++i) {
        const float4 tv = *(const float4*)&tT[i * 36 + n4];
        const float4 u0 = *(const float4*)&sUt[i * 48 + a0];
        const float4 u1 = *(const float4*)&sUt[i * 48 + a0 + 4];
        const float4 u2 = *(const float4*)&sUt[i * 48 + a0 + 8];
        a2[0][0] = fmaf(u0.x, tv.x, a2[0][0]);
        a2[0][1] = fmaf(u0.x, tv.y, a2[0][1]);
        a2[0][2] = fmaf(u0.x, tv.z, a2[0][2]);
        a2[0][3] = fmaf(u0.x, tv.w, a2[0][3]);
        a2[1][0] = fmaf(u0.y, tv.x, a2[1][0]);
        a2[1][1] = fmaf(u0.y, tv.y, a2[1][1]);
        a2[1][2] = fmaf(u0.y, tv.z, a2[1][2]);
        a2[1][3] = fmaf(u0.y, tv.w, a2[1][3]);
        a2[2][0] = fmaf(u0.z, tv.x, a2[2][0]);
        a2[2][1] = fmaf(u0.z, tv.y, a2[2][1]);
        a2[2][2] = fmaf(u0.z, tv.z, a2[2][2]);
        a2[2][3] = fmaf(u0.z, tv.w, a2[2][3]);
        a2[3][0] = fmaf(u0.w, tv.x, a2[3][0]);
        a2[3][1] = fmaf(u0.w, tv.y, a2[3][1]);
        a2[3][2] = fmaf(u0.w, tv.z, a2[3][2]);
        a2[3][3] = fmaf(u0.w, tv.w, a2[3][3]);
        a2[4][0] = fmaf(u1.x, tv.x, a2[4][0]);
        a2[4][1] = fmaf(u1.x, tv.y, a2[4][1]);
        a2[4][2] = fmaf(u1.x, tv.z, a2[4][2]);
        a2[4][3] = fmaf(u1.x, tv.w, a2[4][3]);
        a2[5][0] = fmaf(u1.y, tv.x, a2[5][0]);
        a2[5][1] = fmaf(u1.y, tv.y, a2[5][1]);
        a2[5][2] = fmaf(u1.y, tv.z, a2[5][2]);
        a2[5][3] = fmaf(u1.y, tv.w, a2[5][3]);
        a2[6][0] = fmaf(u1.z, tv.x, a2[6][0]);
        a2[6][1] = fmaf(u1.z, tv.y, a2[6][1]);
        a2[6][2] = fmaf(u1.z, tv.z, a2[6][2]);
        a2[6][3] = fmaf(u1.z, tv.w, a2[6][3]);
        a2[7][0] = fmaf(u1.w, tv.x, a2[7][0]);
        a2[7][1] = fmaf(u1.w, tv.y, a2[7][1]);
        a2[7][2] = fmaf(u1.w, tv.z, a2[7][2]);
        a2[7][3] = fmaf(u1.w, tv.w, a2[7][3]);
        a2[8][0] = fmaf(u2.x, tv.x, a2[8][0]);
        a2[8][1] = fmaf(u2.x, tv.y, a2[8][1]);
        a2[8][2] = fmaf(u2.x, tv.z, a2[8][2]);
        a2[8][3] = fmaf(u2.x, tv.w, a2[8][3]);
        a2[9][0] = fmaf(u2.y, tv.x, a2[9][0]);
        a2[9][1] = fmaf(u2.y, tv.y, a2[9][1]);
        a2[9][2] = fmaf(u2.y, tv.z, a2[9][2]);
        a2[9][3] = fmaf(u2.y, tv.w, a2[9][3]);
        a2[10][0] = fmaf(u2.z, tv.x, a2[10][0]);
        a2[10][1] = fmaf(u2.z, tv.y, a2[10][1]);
        a2[10][2] = fmaf(u2.z, tv.z, a2[10][2]);
        a2[10][3] = fmaf(u2.z, tv.w, a2[10][3]);
        a2[11][0] = fmaf(u2.w, tv.x, a2[11][0]);
        a2[11][1] = fmaf(u2.w, tv.y, a2[11][1]);
        a2[11][2] = fmaf(u2.w, tv.z, a2[11][2]);
        a2[11][3] = fmaf(u2.w, tv.w, a2[11][3]);
    }
    // stores: 8B-aligned everywhere (1410, 30, n4 even) -> float2
    #pragma unroll
    for (int r = 0; r < 12; ++r) {
        const int a = a0 + r;
        if (a < 47) {
            float* p = op + a * 30 + n4;
            *(float2*)p = make_float2(a2[r][0], a2[r][1]);
            if (n4 < 28)
                *(float2*)(p + 2) = make_float2(a2[r][2], a2[r][3]);
        }
    }
}

// ============================================================================
// Main kernel: 4 warps/CTA, 2 images per warp. B gathered early into its own
// smem slab (no buffer reuse); phases are warp-local.
// ============================================================================
__global__ void __launch_bounds__(128) resize_chain_kernel(
    const float* __restrict__ x, float* __restrict__ out) {
    __shared__ __align__(16) float sUV[16 * 48 + 16 * 32];
    __shared__ __align__(16) float sXgA[4][16 * 20];   // [warp][j][i], stride 20
    __shared__ __align__(16) float sXgB[4][16 * 20];   // image B slab
    __shared__ __align__(16) float sT[4][16 * 36];     // [warp][i][n], stride 36

    float* sUt = sUV;          // [i][a]
    float* sVt = sUV + 768;    // [j][n]

    const int t = threadIdx.x;
    const int w = t >> 5;
    const int lane = t & 31;
    const size_t imgA = ((size_t)blockIdx.x * 4 + w) * 2;   // warp's image pair
    const float* __restrict__ xiA = x + imgA * 4096;
    const float* __restrict__ xiB = xiA + 4096;

    const int gi = lane >> 1;            // Xg row this lane gathers
    const int gjb = (lane & 1) << 3;     // Xg col block (8 cols)
    const int n4 = (lane & 7) << 2;
    const int i0 = (lane >> 3) << 2;
    const int a0 = (lane >> 3) * 12;

    float* tT = sT[w];

    // ---- prologue: issue BOTH gathers, stage U/V, park both ----
    float gxA[8], gxB[8];
    {
        const float* rowA = xiA + gi * 256;
        const float* rowB = xiB + gi * 256;
        #pragma unroll
        for (int k = 0; k < 8; ++k) gxA[k] = __ldg(rowA + ((gjb + k) << 2));
        #pragma unroll
        for (int k = 0; k < 8; ++k) gxB[k] = __ldg(rowB + ((gjb + k) << 2));
    }
    for (int v = t; v < 320; v += 128)
        ((float4*)sUV)[v] = ((const float4*)g_UV)[v];
    #pragma unroll
    for (int k = 0; k < 8; ++k) sXgA[w][(gjb + k) * 20 + gi] = gxA[k];
    #pragma unroll
    for (int k = 0; k < 8; ++k) sXgB[w][(gjb + k) * 20 + gi] = gxB[k];
    __syncthreads();

    // ---- image A ----
    phase1(sVt, sXgA[w], tT, n4, i0);
    __syncwarp();
    phase2(sUt, tT, out + imgA * 1410, n4, a0);
    __syncwarp();   // all sT reads of A complete before B's phase1 overwrites

    // ---- image B ----
    phase1(sVt, sXgB[w], tT, n4, i0);
    __syncwarp();
    phase2(sUt, tT, out + (imgA + 1) * 1410, n4, a0);
}

extern "C" void kernel_launch(void* const* d_in, const int* in_sizes, int n_in,
                              void* d_out, int out_size) {
    const float* x = (const float*)d_in[0];
    float* out = (float*)d_out;
    const int imgs = in_sizes[0] / 4096;   // 8192 images of 64x64

    static float hUV[16 * 48 + 16 * 32];
    host_build(hUV);

    cudaMemcpyToSymbolAsync(g_UV, hUV, sizeof(hUV), 0,
                            cudaMemcpyHostToDevice, 0);

    resize_chain_kernel<<<imgs / 8, 128>>>(x, out);
}